// round 15
// baseline (speedup 1.0000x reference)
#include <cuda_runtime.h>
#include <cuda_bf16.h>
#include <mma.h>
#include <math.h>

#define B_ 4
#define N_ 1024
#define H_ 8
#define D_ 256
#define L_ 4
#define DK_ 32
#define NSP_ 512
#define BND (B_*N_*D_)   // 1048576
#define ND  (N_*D_)      // 262144

typedef unsigned long long u64;
typedef unsigned int u32;

using namespace nvcuda;

// ---------------- f32x2 packed-math helpers (sm_100+) ----------------
__device__ __forceinline__ u64 pk2(float x, float y) {
    u64 r; asm("mov.b64 %0, {%1, %2};" : "=l"(r) : "f"(x), "f"(y)); return r;
}
__device__ __forceinline__ float2 upk2(u64 a) {
    float2 f; asm("mov.b64 {%0, %1}, %2;" : "=f"(f.x), "=f"(f.y) : "l"(a)); return f;
}
__device__ __forceinline__ u64 fma2_(u64 a, u64 b, u64 c) {
    u64 d; asm("fma.rn.f32x2 %0, %1, %2, %3;" : "=l"(d) : "l"(a), "l"(b), "l"(c)); return d;
}
__device__ __forceinline__ u64 mul2_(u64 a, u64 b) {
    u64 d; asm("mul.rn.f32x2 %0, %1, %2;" : "=l"(d) : "l"(a), "l"(b)); return d;
}

// ---------------- scratch (static device globals; no allocation) ----------------
__device__ float g_h [BND];
__device__ float g_q [BND];
__device__ float g_k [BND];
__device__ float g_v [BND];
__device__ float g_t1[BND];
__device__ float g_t2[BND];
__device__ float g_node[ND];
__device__ float g_bias[H_ * N_ * N_];                 // bias [H][N][N], log2e-scaled
__device__ __nv_bfloat16 g_wthi[24 * 256 * 256];       // transposed W hi [type*4+layer][n][k]
__device__ __nv_bfloat16 g_wtlo[24 * 256 * 256];       // transposed W lo

// ---------------- prologue: node-level embeddings ----------------
__global__ void node_vec_kernel(const float* __restrict__ svd_emb,
                                const float* __restrict__ W_svd,
                                const float* __restrict__ b_svd,
                                const float* __restrict__ in_deg_emb,
                                const float* __restrict__ out_deg_emb,
                                const int*   __restrict__ in_degrees,
                                const int*   __restrict__ out_degrees,
                                float* __restrict__ nodevec)
{
    int n = blockIdx.x;
    int d = threadIdx.x;
    __shared__ float pos[32];
    if (d < 32) {
        float v = svd_emb[n * 32 + d];
        pos[d] = (d < 16) ? v : -v;
    }
    __syncthreads();
    int in_i  = in_degrees[n];
    int out_i = out_degrees[n];
    float acc = b_svd[d] + in_deg_emb[in_i * D_ + d] + out_deg_emb[out_i * D_ + d];
#pragma unroll
    for (int k = 0; k < 32; k++)
        acc += pos[k] * W_svd[k * D_ + d];
    nodevec[n * D_ + d] = acc;
}

__global__ void add_node_kernel(const float* __restrict__ x,
                                const float* __restrict__ nodevec,
                                float* __restrict__ h)
{
    int i = blockIdx.x * blockDim.x + threadIdx.x;
    h[i] = x[i] + nodevec[i & (ND - 1)];
}

// ---------------- precompute attention bias (scaled by log2(e)) ----------------
__global__ void bias_kernel(const int* __restrict__ spatial_pos,
                            const float* __restrict__ spatial_emb,
                            float* __restrict__ bias)
{
    const float LOG2E = 1.4426950408889634f;
    int i = blockIdx.x * 256 + threadIdx.x;
    int s = spatial_pos[i];
#pragma unroll
    for (int h = 0; h < H_; h++)
        bias[(size_t)h * (N_ * N_) + i] = spatial_emb[s * H_ + h] * LOG2E;
}

// ---------------- precompute transposed bf16 hi/lo weights ----------------
// grid (L*256, 6), 256 threads. Wt[type*4+layer][n][k] = split(W[layer][k][n])
__global__ void wconv_kernel(const float* __restrict__ Wq, const float* __restrict__ Wk,
                             const float* __restrict__ Wv, const float* __restrict__ Wa,
                             const float* __restrict__ W1, const float* __restrict__ W2,
                             __nv_bfloat16* __restrict__ hi, __nv_bfloat16* __restrict__ lo)
{
    const float* Ws[6] = {Wq, Wk, Wv, Wa, W1, W2};
    const float* W = Ws[blockIdx.y];
    int l = blockIdx.x >> 8;
    int n = blockIdx.x & 255;
    int k = threadIdx.x;
    float x = W[(size_t)l * 65536 + (size_t)k * 256 + n];
    __nv_bfloat16 h = __float2bfloat16(x);
    float r = x - __bfloat162float(h);
    size_t o = (((size_t)blockIdx.y * 4 + l) * 256 + n) * 256 + k;
    hi[o] = h;
    lo[o] = __float2bfloat16(r);
}

// ---------------- WMMA GEMM: 128x64 tile, bf16 hi/lo split, tensor pipe ----------------
// smem (dynamic, bytes):
//   sAh @ 0      : 128 x 72 bf16 = 18432
//   sAl @ 18432  : 128 x 72 bf16 = 18432
//   sBh @ 36864  :  64 x 72 bf16 =  9216
//   sBl @ 46080  :  64 x 72 bf16 =  9216
//   out_s reuses [0, 36864): 128 x 72 f32
#define SMA_LD 72
#define OFF_AH 0
#define OFF_AL 18432
#define OFF_BH 36864
#define OFF_BL 46080
#define SM_WM_TOTAL 55296

__device__ __forceinline__ void split2w(float x, float y, u32& h, u32& lo) {
    __nv_bfloat162 hh = __float22bfloat162_rn(make_float2(x, y));
    float fx = __low2float(hh);
    float fy = __high2float(hh);
    __nv_bfloat162 ll = __float22bfloat162_rn(make_float2(x - fx, y - fy));
    h  = *reinterpret_cast<u32*>(&hh);
    lo = *reinterpret_cast<u32*>(&ll);
}

__device__ __forceinline__ void gemm_wm_body(const float* __restrict__ A,
                                             const __nv_bfloat16* __restrict__ wthi,
                                             const __nv_bfloat16* __restrict__ wtlo,
                                             const float* __restrict__ bias,
                                             const float* __restrict__ res,
                                             float* __restrict__ out,
                                             int relu, int bm, int bn, char* smem)
{
    __nv_bfloat16* sAh = reinterpret_cast<__nv_bfloat16*>(smem + OFF_AH);
    __nv_bfloat16* sAl = reinterpret_cast<__nv_bfloat16*>(smem + OFF_AL);
    __nv_bfloat16* sBh = reinterpret_cast<__nv_bfloat16*>(smem + OFF_BH);
    __nv_bfloat16* sBl = reinterpret_cast<__nv_bfloat16*>(smem + OFF_BL);
    float* out_s = reinterpret_cast<float*>(smem);

    int tid = threadIdx.x;              // 256
    int wid = tid >> 5;                 // 0..7
    int wm  = wid >> 1;                 // 0..3 (m dir)
    int wn  = wid & 1;                  // 0..1 (n dir)

    wmma::fragment<wmma::accumulator, 16, 16, 16, float> acc[2][2];
#pragma unroll
    for (int i = 0; i < 2; i++)
#pragma unroll
        for (int j = 0; j < 2; j++)
            wmma::fill_fragment(acc[i][j], 0.0f);

    // A fill indices: row = tid>>1, k-half = (tid&1)*32
    int arow = tid >> 1;
    int akb  = (tid & 1) * 32;
    // B fill indices: n = tid>>2, k-slot = (tid&3)*16
    int bnr = tid >> 2;
    int bks = (tid & 3) * 16;

#pragma unroll 1
    for (int kc = 0; kc < 4; kc++) {
        int k0 = kc * 64;
        // stage A (fp32 -> bf16 hi/lo)
        {
            const float* ap = A + (size_t)(bm + arow) * 256 + k0 + akb;
#pragma unroll
            for (int j = 0; j < 8; j++) {
                float4 x = *reinterpret_cast<const float4*>(ap + j * 4);
                u32 h0, h1, l0, l1;
                split2w(x.x, x.y, h0, l0);
                split2w(x.z, x.w, h1, l1);
                int e = arow * SMA_LD + akb + j * 4;
                *reinterpret_cast<uint2*>(&sAh[e]) = make_uint2(h0, h1);
                *reinterpret_cast<uint2*>(&sAl[e]) = make_uint2(l0, l1);
            }
        }
        // stage B (preconverted bf16)
        {
            const __nv_bfloat16* bh = wthi + (size_t)(bn + bnr) * 256 + k0 + bks;
            const __nv_bfloat16* bl = wtlo + (size_t)(bn + bnr) * 256 + k0 + bks;
            uint4 h0 = *reinterpret_cast<const uint4*>(bh);
            uint4 h1 = *reinterpret_cast<const uint4*>(bh + 8);
            uint4 l0 = *reinterpret_cast<const uint4*>(bl);
            uint4 l1 = *reinterpret_cast<const uint4*>(bl + 8);
            int e = bnr * SMA_LD + bks;
            *reinterpret_cast<uint4*>(&sBh[e])     = h0;
            *reinterpret_cast<uint4*>(&sBh[e + 8]) = h1;
            *reinterpret_cast<uint4*>(&sBl[e])     = l0;
            *reinterpret_cast<uint4*>(&sBl[e + 8]) = l1;
        }
        __syncthreads();

#pragma unroll
        for (int ks = 0; ks < 4; ks++) {
            int kk = ks * 16;
            wmma::fragment<wmma::matrix_a, 16, 16, 16, __nv_bfloat16, wmma::row_major> ah[2], al[2];
            wmma::fragment<wmma::matrix_b, 16, 16, 16, __nv_bfloat16, wmma::col_major> bh[2], bl[2];
#pragma unroll
            for (int i = 0; i < 2; i++) {
                int m0 = wm * 32 + i * 16;
                wmma::load_matrix_sync(ah[i], &sAh[m0 * SMA_LD + kk], SMA_LD);
                wmma::load_matrix_sync(al[i], &sAl[m0 * SMA_LD + kk], SMA_LD);
            }
#pragma unroll
            for (int j = 0; j < 2; j++) {
                int n0 = wn * 32 + j * 16;
                wmma::load_matrix_sync(bh[j], &sBh[n0 * SMA_LD + kk], SMA_LD);
                wmma::load_matrix_sync(bl[j], &sBl[n0 * SMA_LD + kk], SMA_LD);
            }
#pragma unroll
            for (int i = 0; i < 2; i++)
#pragma unroll
                for (int j = 0; j < 2; j++) {
                    wmma::mma_sync(acc[i][j], ah[i], bh[j], acc[i][j]);
                    wmma::mma_sync(acc[i][j], ah[i], bl[j], acc[i][j]);
                    wmma::mma_sync(acc[i][j], al[i], bh[j], acc[i][j]);
                }
        }
        __syncthreads();
    }

    // stage accumulators to smem (reuses A region)
#pragma unroll
    for (int i = 0; i < 2; i++)
#pragma unroll
        for (int j = 0; j < 2; j++) {
            int m0 = wm * 32 + i * 16;
            int n0 = wn * 32 + j * 16;
            wmma::store_matrix_sync(&out_s[m0 * SMA_LD + n0], acc[i][j], SMA_LD,
                                    wmma::mem_row_major);
        }
    __syncthreads();

    // epilogue: bias (+res) (relu), vectorized
    {
        int row = tid >> 1;
        int cb  = (tid & 1) * 32;
        int m = bm + row;
        float* orow = out + (size_t)m * 256 + bn + cb;
        const float* rrow = res ? res + (size_t)m * 256 + bn + cb : (const float*)0;
#pragma unroll
        for (int c = 0; c < 32; c += 4) {
            float4 bb = *reinterpret_cast<const float4*>(bias + bn + cb + c);
            float4 vv;
            vv.x = out_s[row * SMA_LD + cb + c + 0] + bb.x;
            vv.y = out_s[row * SMA_LD + cb + c + 1] + bb.y;
            vv.z = out_s[row * SMA_LD + cb + c + 2] + bb.z;
            vv.w = out_s[row * SMA_LD + cb + c + 3] + bb.w;
            if (rrow) {
                float4 rr = *reinterpret_cast<const float4*>(rrow + c);
                vv.x += rr.x; vv.y += rr.y; vv.z += rr.z; vv.w += rr.w;
            }
            if (relu) {
                vv.x = fmaxf(vv.x, 0.f); vv.y = fmaxf(vv.y, 0.f);
                vv.z = fmaxf(vv.z, 0.f); vv.w = fmaxf(vv.w, 0.f);
            }
            *reinterpret_cast<float4*>(orow + c) = vv;
        }
    }
}

__global__ void __launch_bounds__(256)
gemm_wm_kernel(const float* __restrict__ A,
               const __nv_bfloat16* __restrict__ wthi,
               const __nv_bfloat16* __restrict__ wtlo,
               const float* __restrict__ bias,
               const float* __restrict__ res,
               float* __restrict__ out, int relu)
{
    extern __shared__ char smem[];
    gemm_wm_body(A, wthi, wtlo, bias, res, out, relu,
                 blockIdx.x * 128, blockIdx.y * 64, smem);
}

__global__ void __launch_bounds__(256)
qkv_wm_kernel(const float* __restrict__ A,
              const __nv_bfloat16* __restrict__ wthiB,
              const __nv_bfloat16* __restrict__ wtloB,
              int layer,
              const float* __restrict__ bq, const float* __restrict__ bk, const float* __restrict__ bv,
              float* __restrict__ q, float* __restrict__ k, float* __restrict__ v)
{
    extern __shared__ char smem[];
    int t = blockIdx.z;
    const __nv_bfloat16* hi = wthiB + ((size_t)(t * 4 + layer)) * 65536;
    const __nv_bfloat16* lo = wtloB + ((size_t)(t * 4 + layer)) * 65536;
    const float* bias = (t == 0) ? bq : ((t == 1) ? bk : bv);
    float* out = (t == 0) ? q : ((t == 1) ? k : v);
    gemm_wm_body(A, hi, lo, bias, (const float*)0, out, 0,
                 blockIdx.x * 128, blockIdx.y * 64, smem);
}

// ---------------- flash attention (R12 best): lane = query, double-buffered, exp2 ----------------
__global__ void __launch_bounds__(128)
attn_kernel(const float* __restrict__ q,
            const float* __restrict__ k,
            const float* __restrict__ v,
            const float* __restrict__ bias,   // [H][N][N], log2e-scaled
            float* __restrict__ out)
{
    int bh = blockIdx.y;
    int b  = bh >> 3;
    int h  = bh & 7;
    int q0 = blockIdx.x * 128;

    __shared__ __align__(16) float Ks[2][32][36];
    __shared__ __align__(16) float Vs[2][32][36];

    int tid  = threadIdx.x;
    int w    = tid >> 5;
    int lane = tid & 31;
    int qrow = w * 32 + lane;
    int qi   = q0 + qrow;

    int fr0 = tid >> 3;
    int fc0 = (tid & 7) * 4;
    int fr1 = fr0 + 16;

    const float scale = 0.1767766952966369f * 1.4426950408889634f;

    u64 qv2[16], o2[16];
    {
        const float4* qp = reinterpret_cast<const float4*>(
            q + ((size_t)(b * N_ + qi)) * D_ + h * DK_);
#pragma unroll
        for (int d4 = 0; d4 < 8; d4++) {
            float4 t = qp[d4];
            qv2[d4*2+0] = pk2(t.x * scale, t.y * scale);
            qv2[d4*2+1] = pk2(t.z * scale, t.w * scale);
        }
    }
#pragma unroll
    for (int d = 0; d < 16; d++) o2[d] = 0ull;
    float m = -1e30f, l = 0.0f;

    const float* brow = bias + (size_t)h * (N_ * N_) + (size_t)qi * N_;

    float4 kf0, kf1, vf0, vf1, bf[8];

    {
        const float* kb = k + ((size_t)(b * N_)) * D_ + h * DK_;
        const float* vb = v + ((size_t)(b * N_)) * D_ + h * DK_;
        kf0 = *reinterpret_cast<const float4*>(kb + (size_t)fr0 * D_ + fc0);
        kf1 = *reinterpret_cast<const float4*>(kb + (size_t)fr1 * D_ + fc0);
        vf0 = *reinterpret_cast<const float4*>(vb + (size_t)fr0 * D_ + fc0);
        vf1 = *reinterpret_cast<const float4*>(vb + (size_t)fr1 * D_ + fc0);
#pragma unroll
        for (int j = 0; j < 8; j++)
            bf[j] = *reinterpret_cast<const float4*>(brow + j * 4);
        *reinterpret_cast<float4*>(&Ks[0][fr0][fc0]) = kf0;
        *reinterpret_cast<float4*>(&Ks[0][fr1][fc0]) = kf1;
        *reinterpret_cast<float4*>(&Vs[0][fr0][fc0]) = vf0;
        *reinterpret_cast<float4*>(&Vs[0][fr1][fc0]) = vf1;
    }
    __syncthreads();

#pragma unroll 1
    for (int t = 0; t < 32; t++) {
        int cur = t & 1;
        int k0n = (t + 1) * 32;

        float s[32];
#pragma unroll
        for (int j = 0; j < 8; j++) {
            s[j*4+0] = bf[j].x; s[j*4+1] = bf[j].y;
            s[j*4+2] = bf[j].z; s[j*4+3] = bf[j].w;
        }

        if (t < 31) {
            const float* kb = k + ((size_t)(b * N_ + k0n)) * D_ + h * DK_;
            const float* vb = v + ((size_t)(b * N_ + k0n)) * D_ + h * DK_;
            kf0 = *reinterpret_cast<const float4*>(kb + (size_t)fr0 * D_ + fc0);
            kf1 = *reinterpret_cast<const float4*>(kb + (size_t)fr1 * D_ + fc0);
            vf0 = *reinterpret_cast<const float4*>(vb + (size_t)fr0 * D_ + fc0);
            vf1 = *reinterpret_cast<const float4*>(vb + (size_t)fr1 * D_ + fc0);
#pragma unroll
            for (int j = 0; j < 8; j++)
                bf[j] = *reinterpret_cast<const float4*>(brow + k0n + j * 4);
        }

#pragma unroll
        for (int kk = 0; kk < 32; kk++) {
            u64 svA = 0ull, svB = 0ull;
            const ulonglong2* kr = reinterpret_cast<const ulonglong2*>(&Ks[cur][kk][0]);
#pragma unroll
            for (int p = 0; p < 8; p++) {
                ulonglong2 kp = kr[p];
                svA = fma2_(qv2[2*p + 0], kp.x, svA);
                svB = fma2_(qv2[2*p + 1], kp.y, svB);
            }
            float2 sa = upk2(svA);
            float2 sb = upk2(svB);
            s[kk] += (sa.x + sa.y) + (sb.x + sb.y);
        }

        float x0 = s[0], x1 = s[1], x2 = s[2], x3 = s[3];
#pragma unroll
        for (int j = 4; j < 32; j += 4) {
            x0 = fmaxf(x0, s[j]);     x1 = fmaxf(x1, s[j + 1]);
            x2 = fmaxf(x2, s[j + 2]); x3 = fmaxf(x3, s[j + 3]);
        }
        float tmax = fmaxf(fmaxf(x0, x1), fmaxf(x2, x3));
        float mnew  = fmaxf(m, tmax);
        float alpha = exp2f(m - mnew);

        float p0 = 0.f, p1 = 0.f, p2 = 0.f, p3 = 0.f;
#pragma unroll
        for (int j = 0; j < 32; j += 4) {
            float e0 = exp2f(s[j]     - mnew);
            float e1 = exp2f(s[j + 1] - mnew);
            float e2 = exp2f(s[j + 2] - mnew);
            float e3 = exp2f(s[j + 3] - mnew);
            s[j] = e0; s[j + 1] = e1; s[j + 2] = e2; s[j + 3] = e3;
            p0 += e0; p1 += e1; p2 += e2; p3 += e3;
        }
        l = l * alpha + ((p0 + p1) + (p2 + p3));
        m = mnew;

        u64 al2 = pk2(alpha, alpha);
#pragma unroll
        for (int d = 0; d < 16; d++) o2[d] = mul2_(o2[d], al2);

#pragma unroll
        for (int kk = 0; kk < 32; kk++) {
            u64 p2k = pk2(s[kk], s[kk]);
            const ulonglong2* vr = reinterpret_cast<const ulonglong2*>(&Vs[cur][kk][0]);
#pragma unroll
            for (int p = 0; p < 8; p++) {
                ulonglong2 vp = vr[p];
                o2[2*p + 0] = fma2_(p2k, vp.x, o2[2*p + 0]);
                o2[2*p + 1] = fma2_(p2k, vp.y, o2[2*p + 1]);
            }
        }

        if (t < 31) {
            int nxt = 1 - cur;
            *reinterpret_cast<float4*>(&Ks[nxt][fr0][fc0]) = kf0;
            *reinterpret_cast<float4*>(&Ks[nxt][fr1][fc0]) = kf1;
            *reinterpret_cast<float4*>(&Vs[nxt][fr0][fc0]) = vf0;
            *reinterpret_cast<float4*>(&Vs[nxt][fr1][fc0]) = vf1;
        }
        __syncthreads();
    }

    float inv = 1.0f / l;
    float* ob = out + ((size_t)(b * N_ + qi)) * D_ + h * DK_;
#pragma unroll
    for (int d4 = 0; d4 < 8; d4++) {
        float2 t0 = upk2(o2[d4*2 + 0]);
        float2 t1 = upk2(o2[d4*2 + 1]);
        float4 t;
        t.x = t0.x * inv; t.y = t0.y * inv;
        t.z = t1.x * inv; t.w = t1.y * inv;
        *reinterpret_cast<float4*>(ob + d4 * 4) = t;
    }
}

// ---------------- LayerNorm over D=256 ----------------
__global__ void __launch_bounds__(256)
ln_kernel(const float* __restrict__ z,
          const float* __restrict__ g,
          const float* __restrict__ bta,
          float* __restrict__ out)
{
    int row = blockIdx.x;
    int t   = threadIdx.x;
    int lane = t & 31, wid = t >> 5;
    __shared__ float red1[8], red2[8];

    float vv = z[(size_t)row * 256 + t];
    float s = vv;
#pragma unroll
    for (int off = 16; off; off >>= 1) s += __shfl_xor_sync(0xffffffffu, s, off);
    if (lane == 0) red1[wid] = s;
    __syncthreads();
    float tot = 0.0f;
#pragma unroll
    for (int i = 0; i < 8; i++) tot += red1[i];
    float mu = tot * (1.0f / 256.0f);

    float d = vv - mu;
    float sq = d * d;
#pragma unroll
    for (int off = 16; off; off >>= 1) sq += __shfl_xor_sync(0xffffffffu, sq, off);
    if (lane == 0) red2[wid] = sq;
    __syncthreads();
    float var = 0.0f;
#pragma unroll
    for (int i = 0; i < 8; i++) var += red2[i];
    var *= (1.0f / 256.0f);

    out[(size_t)row * 256 + t] = d * rsqrtf(var + 1e-6f) * g[t] + bta[t];
}

// ---------------- launch ----------------
extern "C" void kernel_launch(void* const* d_in, const int* in_sizes, int n_in,
                              void* d_out, int out_size)
{
    (void)n_in; (void)out_size;

    const float *x, *svd_emb, *W_svd, *b_svd, *in_deg_emb, *out_deg_emb, *spatial_emb;
    const float *Wq, *Wk, *Wv, *Wa, *W1, *W2;
    const float *bq, *bk, *bv, *ba, *b1, *b2;
    const float *ln1_g, *ln1_b, *ln2_g, *ln2_b;
    const int *in_degrees, *out_degrees, *spatial_pos;

    if (in_sizes[1] == 1024) {
        // setup_inputs dict order
        x           = (const float*)d_in[0];
        in_degrees  = (const int*)  d_in[1];
        out_degrees = (const int*)  d_in[2];
        spatial_pos = (const int*)  d_in[3];
        svd_emb     = (const float*)d_in[4];
        in_deg_emb  = (const float*)d_in[5];
        out_deg_emb = (const float*)d_in[6];
        spatial_emb = (const float*)d_in[7];
        W_svd       = (const float*)d_in[8];
        b_svd       = (const float*)d_in[9];
        Wq = (const float*)d_in[10]; Wk = (const float*)d_in[11];
        Wv = (const float*)d_in[12]; Wa = (const float*)d_in[13];
        W1 = (const float*)d_in[14]; W2 = (const float*)d_in[15];
        bq = (const float*)d_in[16]; bk = (const float*)d_in[17];
        bv = (const float*)d_in[18]; ba = (const float*)d_in[19];
        b1 = (const float*)d_in[20]; b2 = (const float*)d_in[21];
        ln1_b = (const float*)d_in[22]; ln2_b = (const float*)d_in[23];
        ln1_g = (const float*)d_in[24]; ln2_g = (const float*)d_in[25];
    } else {
        // reference() signature order
        x           = (const float*)d_in[0];
        svd_emb     = (const float*)d_in[1];
        W_svd       = (const float*)d_in[2];
        b_svd       = (const float*)d_in[3];
        in_deg_emb  = (const float*)d_in[4];
        out_deg_emb = (const float*)d_in[5];
        spatial_emb = (const float*)d_in[6];
        Wq = (const float*)d_in[7];  bq = (const float*)d_in[8];
        Wk = (const float*)d_in[9];  bk = (const float*)d_in[10];
        Wv = (const float*)d_in[11]; bv = (const float*)d_in[12];
        Wa = (const float*)d_in[13]; ba = (const float*)d_in[14];
        ln1_g = (const float*)d_in[15]; ln1_b = (const float*)d_in[16];
        W1 = (const float*)d_in[17]; b1 = (const float*)d_in[18];
        W2 = (const float*)d_in[19]; b2 = (const float*)d_in[20];
        ln2_g = (const float*)d_in[21]; ln2_b = (const float*)d_in[22];
        in_degrees  = (const int*)d_in[23];
        out_degrees = (const int*)d_in[24];
        spatial_pos = (const int*)d_in[25];
    }

    float *hB, *qB, *kB, *vB, *t1B, *t2B, *nodeB, *biasB;
    __nv_bfloat16 *wthiB, *wtloB;
    cudaGetSymbolAddress((void**)&hB,    g_h);
    cudaGetSymbolAddress((void**)&qB,    g_q);
    cudaGetSymbolAddress((void**)&kB,    g_k);
    cudaGetSymbolAddress((void**)&vB,    g_v);
    cudaGetSymbolAddress((void**)&t1B,   g_t1);
    cudaGetSymbolAddress((void**)&t2B,   g_t2);
    cudaGetSymbolAddress((void**)&nodeB, g_node);
    cudaGetSymbolAddress((void**)&biasB, g_bias);
    cudaGetSymbolAddress((void**)&wthiB, g_wthi);
    cudaGetSymbolAddress((void**)&wtloB, g_wtlo);

    float* outp = (float*)d_out;

    cudaFuncSetAttribute(gemm_wm_kernel, cudaFuncAttributeMaxDynamicSharedMemorySize, SM_WM_TOTAL);
    cudaFuncSetAttribute(qkv_wm_kernel,  cudaFuncAttributeMaxDynamicSharedMemorySize, SM_WM_TOTAL);

    // prologue
    node_vec_kernel<<<N_, 256>>>(svd_emb, W_svd, b_svd, in_deg_emb, out_deg_emb,
                                 in_degrees, out_degrees, nodeB);
    add_node_kernel<<<BND / 256, 256>>>(x, nodeB, hB);
    bias_kernel<<<(N_ * N_) / 256, 256>>>(spatial_pos, spatial_emb, biasB);
    {
        dim3 wgrid(L_ * 256, 6);
        wconv_kernel<<<wgrid, 256>>>(Wq, Wk, Wv, Wa, W1, W2, wthiB, wtloB);
    }

    dim3 ggrid(B_ * N_ / 128, D_ / 64);        // (32, 4)
    dim3 qkvgrid(B_ * N_ / 128, D_ / 64, 3);   // (32, 4, 3)
    dim3 agrid(N_ / 128, B_ * H_);             // (8, 32)

    for (int l = 0; l < L_; l++) {
        qkv_wm_kernel<<<qkvgrid, 256, SM_WM_TOTAL>>>(hB, wthiB, wtloB, l,
                                                     bq + l * D_, bk + l * D_, bv + l * D_,
                                                     qB, kB, vB);

        attn_kernel<<<agrid, 128>>>(qB, kB, vB, biasB, t1B);

        gemm_wm_kernel<<<ggrid, 256, SM_WM_TOTAL>>>(t1B,
            wthiB + ((size_t)(3 * 4 + l)) * 65536, wtloB + ((size_t)(3 * 4 + l)) * 65536,
            ba + l * D_, hB, t2B, 0);
        ln_kernel<<<B_ * N_, 256>>>(t2B, ln1_g + l * D_, ln1_b + l * D_, hB);

        gemm_wm_kernel<<<ggrid, 256, SM_WM_TOTAL>>>(hB,
            wthiB + ((size_t)(4 * 4 + l)) * 65536, wtloB + ((size_t)(4 * 4 + l)) * 65536,
            b1 + l * D_, nullptr, t1B, 1);
        gemm_wm_kernel<<<ggrid, 256, SM_WM_TOTAL>>>(t1B,
            wthiB + ((size_t)(5 * 4 + l)) * 65536, wtloB + ((size_t)(5 * 4 + l)) * 65536,
            b2 + l * D_, hB, t2B, 0);

        float* ln2_dst = (l == L_ - 1) ? outp : hB;
        ln_kernel<<<B_ * N_, 256>>>(t2B, ln2_g + l * D_, ln2_b + l * D_, ln2_dst);
    }
}